// round 2
// baseline (speedup 1.0000x reference)
#include <cuda_runtime.h>
#include <math.h>
#include <float.h>

// ---------------- problem constants ----------------
#define R4    4           // fold regions
#define HH    64          // input feature H
#define WW0   216         // input feature W
#define HWP   (HH*WW0)    // 13824 pixels
#define HF    32          // folded H
#define WF    108         // folded W
#define KP    (HF*WF)     // 3456 pixels per region
#define C64   64          // channels
#define NP    8192        // points
#define MCAP  4096        // M = N / FOLD_H
#define CH_LEN 512
#define NCHUNK 9
#define MPAD  (NCHUNK*CH_LEN)   // 4608 padded rows

// ---------------- scratch (device globals; no allocation) ----------------
__device__ float g_featP[R4][KP][C64];   // folded feat, pixel-major
__device__ float g_valP [R4][KP][C64];   // folded value, pixel-major
__device__ float g_invx [R4][KP];        // 1/max(||feat_pixel||,1e-12)
__device__ float g_cnA  [R4][MPAD][C64]; // alpha * normalized centers (+dead row at cnt)
__device__ float g_vc   [R4][MCAP][C64]; // value centers
__device__ int   g_cnt  [R4];
__device__ float g_ppx  [R4][MCAP];
__device__ float g_ppy  [R4][MCAP];
__device__ int   g_pr   [NP];
__device__ int   g_ppos [NP];
__device__ float g_bestv[R4][NCHUNK][KP];
__device__ int   g_bestm[R4][NCHUNK][KP];
__device__ float g_agg  [R4][MCAP][C64];
__device__ float g_den  [R4][MCAP];

// ---------------- Kernel A: 1x1 conv (feat & value) + fold, pixel-major store ----------------
__global__ __launch_bounds__(256) void kA(const float* __restrict__ x,
                                          const float* __restrict__ Wf, const float* __restrict__ bf,
                                          const float* __restrict__ Wv, const float* __restrict__ bv) {
    __shared__ float xs [64][64];   // element (c,pl) at [c][(pl+c)&63]
    __shared__ float wfs[64][64];   // element (c,o)  at [c][(o+c)&63]
    __shared__ float wvs[64][64];
    int tx = threadIdx.x;
    int p0 = blockIdx.x * 64;
    #pragma unroll
    for (int j = 0; j < 16; j++) {
        int idx = tx + j * 256;
        int o = idx >> 6, c = idx & 63;
        wfs[c][(o + c) & 63] = Wf[idx];
        wvs[c][(o + c) & 63] = Wv[idx];
    }
    #pragma unroll
    for (int j = 0; j < 16; j++) {
        int idx = tx + j * 256;
        int c = idx >> 6, pl = idx & 63;
        xs[c][(pl + c) & 63] = x[c * HWP + p0 + pl];
    }
    __syncthreads();
    int o  = tx & 63;
    int pg = tx >> 6;             // 4 pixel groups of 16
    float accf[16], accv[16];
    float bfo = bf[o], bvo = bv[o];
    #pragma unroll
    for (int i = 0; i < 16; i++) { accf[i] = bfo; accv[i] = bvo; }
    #pragma unroll
    for (int c = 0; c < 64; c++) {
        float wfv = wfs[c][(o + c) & 63];
        float wvv = wvs[c][(o + c) & 63];
        #pragma unroll
        for (int i = 0; i < 16; i++) {
            float xv = xs[c][((pg * 16 + i) + c) & 63];
            accf[i] += wfv * xv;
            accv[i] += wvv * xv;
        }
    }
    #pragma unroll
    for (int i = 0; i < 16; i++) {
        int p = p0 + pg * 16 + i;
        int h = p / WW0, w = p % WW0;
        int r = ((h >= HF) ? 2 : 0) + ((w >= WF) ? 1 : 0);
        int loc = (h & 31) * WF + (w >= WF ? w - WF : w);
        g_featP[r][loc][o] = accf[i];
        g_valP [r][loc][o] = accv[i];
    }
}

// ---------------- Kernel B: per-pixel inverse norm ----------------
__global__ __launch_bounds__(256) void kB() {
    int wid = blockIdx.x * 8 + (threadIdx.x >> 5);
    int lane = threadIdx.x & 31;
    int r = wid / KP, k = wid % KP;
    float a = g_featP[r][k][lane];
    float b = g_featP[r][k][lane + 32];
    float ss = a * a + b * b;
    #pragma unroll
    for (int off = 16; off > 0; off >>= 1) ss += __shfl_xor_sync(0xffffffffu, ss, off);
    if (lane == 0) g_invx[r][k] = 1.0f / fmaxf(sqrtf(ss), 1e-12f);
}

// ---------------- Kernel C: point region partition + stable compaction ----------------
__global__ __launch_bounds__(1024) void kC(const float* __restrict__ pts) {
    __shared__ int sc[4][1024];
    int t = threadIdx.x;
    float mx[8], my[8]; int mr[8];
    int lc[4] = {0, 0, 0, 0};
    #pragma unroll
    for (int i = 0; i < 8; i++) {
        int n = t * 8 + i;
        float px = pts[2 * n], py = pts[2 * n + 1];
        int ri = -1;
        if (px > 0.0f && px <= 1296.0f && py > 0.0f && py <= 384.0f)
            ri = ((py > 192.0f) ? 2 : 0) + ((px > 648.0f) ? 1 : 0);
        mx[i] = px; my[i] = py; mr[i] = ri;
        if (ri >= 0) lc[ri]++;
    }
    #pragma unroll
    for (int r = 0; r < 4; r++) sc[r][t] = lc[r];
    __syncthreads();
    for (int off = 1; off < 1024; off <<= 1) {
        int tv[4];
        #pragma unroll
        for (int r = 0; r < 4; r++) tv[r] = (t >= off) ? sc[r][t - off] : 0;
        __syncthreads();
        #pragma unroll
        for (int r = 0; r < 4; r++) sc[r][t] += tv[r];
        __syncthreads();
    }
    int ex[4];
    #pragma unroll
    for (int r = 0; r < 4; r++) ex[r] = sc[r][t] - lc[r];
    #pragma unroll
    for (int i = 0; i < 8; i++) {
        int n = t * 8 + i; int ri = mr[i];
        if (ri < 0) { g_pr[n] = -1; g_ppos[n] = 0; }
        else {
            int pos = ex[ri]++;
            g_pr[n] = ri; g_ppos[n] = pos;
            if (pos < MCAP) { g_ppx[ri][pos] = mx[i]; g_ppy[ri][pos] = my[i]; }
        }
    }
    if (t < 4) g_cnt[t] = sc[t][1023];
}

// ---------------- Kernel D: bilinear gather of centers (+dead row), normalize ----------------
__global__ __launch_bounds__(128) void kD(const float* __restrict__ sim_alpha) {
    int r = blockIdx.y;
    int cnt = min(g_cnt[r], MCAP);
    int m = blockIdx.x * 4 + (threadIdx.x >> 5);
    int lane = threadIdx.x & 31;
    if (m > cnt) return;
    float f0, f1, v0 = 0.f, v1 = 0.f;
    if (m == cnt) {               // dead row: grid (-1,-1) -> corner pixel (0,0)
        f0 = g_featP[r][0][lane];
        f1 = g_featP[r][0][lane + 32];
    } else {
        float px = g_ppx[r][m], py = g_ppy[r][m];
        float gx = ((px / 1295.0f) * 2.0f - 1.0f + 1.0f) * 54.0f - 0.5f;
        float gy = ((py / 383.0f)  * 2.0f - 1.0f + 1.0f) * 16.0f - 0.5f;
        float x0 = floorf(gx), y0 = floorf(gy);
        float wx = gx - x0, wy = gy - y0;
        int ix0 = (int)fminf(fmaxf(x0,        0.f), 107.f);
        int ix1 = (int)fminf(fmaxf(x0 + 1.0f, 0.f), 107.f);
        int iy0 = (int)fminf(fmaxf(y0,        0.f), 31.f);
        int iy1 = (int)fminf(fmaxf(y0 + 1.0f, 0.f), 31.f);
        float w00 = (1.f - wx) * (1.f - wy), w01 = wx * (1.f - wy);
        float w10 = (1.f - wx) * wy,         w11 = wx * wy;
        int p00 = iy0 * WF + ix0, p01 = iy0 * WF + ix1;
        int p10 = iy1 * WF + ix0, p11 = iy1 * WF + ix1;
        f0 = w00 * g_featP[r][p00][lane]      + w01 * g_featP[r][p01][lane]
           + w10 * g_featP[r][p10][lane]      + w11 * g_featP[r][p11][lane];
        f1 = w00 * g_featP[r][p00][lane + 32] + w01 * g_featP[r][p01][lane + 32]
           + w10 * g_featP[r][p10][lane + 32] + w11 * g_featP[r][p11][lane + 32];
        v0 = w00 * g_valP[r][p00][lane]       + w01 * g_valP[r][p01][lane]
           + w10 * g_valP[r][p10][lane]       + w11 * g_valP[r][p11][lane];
        v1 = w00 * g_valP[r][p00][lane + 32]  + w01 * g_valP[r][p01][lane + 32]
           + w10 * g_valP[r][p10][lane + 32]  + w11 * g_valP[r][p11][lane + 32];
    }
    float ss = f0 * f0 + f1 * f1;
    #pragma unroll
    for (int off = 16; off > 0; off >>= 1) ss += __shfl_xor_sync(0xffffffffu, ss, off);
    float inv = 1.0f / fmaxf(sqrtf(ss), 1e-12f);
    float a = sim_alpha[0] * inv;
    g_cnA[r][m][lane]      = a * f0;
    g_cnA[r][m][lane + 32] = a * f1;
    if (m < cnt) {
        g_vc[r][m][lane]      = v0;
        g_vc[r][m][lane + 32] = v1;
    }
}

// ---------------- Kernel Z: zero agg/den ----------------
__global__ void kZ() {
    int i = blockIdx.x * blockDim.x + threadIdx.x;
    if (i < R4 * MCAP * C64) ((float*)g_agg)[i] = 0.f;
    if (i < R4 * MCAP)       ((float*)g_den)[i] = 0.f;
}

// ---------------- Kernel E: sim GEMM + fused per-column (chunked) argmax ----------------
__global__ __launch_bounds__(256) void kE() {
    int r = blockIdx.z, ch = blockIdx.y;
    int k0 = blockIdx.x * 64;
    int cnt = min(g_cnt[r], MCAP);
    int Mr = cnt + (cnt < MCAP ? 1 : 0);     // +1 dead row
    int tx = threadIdx.x;
    int kg = tx & 15, mg = tx >> 4;
    __shared__ __align__(16) float As[64][68];
    __shared__ __align__(16) float Bs[64][68];
    __shared__ float rv[16][64];
    __shared__ int   rm[16][64];
    float bv[4]; int bm[4];
    #pragma unroll
    for (int i = 0; i < 4; i++) { bv[i] = -FLT_MAX; bm[i] = 0x7fffffff; }
    int mbase = ch * CH_LEN;
    if (mbase < Mr) {
        #pragma unroll
        for (int j = 0; j < 16; j++) {
            int idx = tx + j * 256;
            int c = idx & 63, kl = idx >> 6;
            Bs[c][kl] = g_featP[r][k0 + kl][c];
        }
        for (int mt = 0; mt < 8; mt++) {
            int m0 = mbase + mt * 64;
            if (m0 >= Mr) break;
            __syncthreads();
            #pragma unroll
            for (int j = 0; j < 16; j++) {
                int idx = tx + j * 256;
                int c = idx & 63, ml = idx >> 6;
                As[c][ml] = g_cnA[r][m0 + ml][c];
            }
            __syncthreads();
            float acc[4][4];
            #pragma unroll
            for (int a = 0; a < 4; a++)
                #pragma unroll
                for (int b = 0; b < 4; b++) acc[a][b] = 0.f;
            #pragma unroll
            for (int c = 0; c < 64; c++) {
                float4 av = *reinterpret_cast<const float4*>(&As[c][mg * 4]);
                float4 bvv = *reinterpret_cast<const float4*>(&Bs[c][kg * 4]);
                acc[0][0] += av.x * bvv.x; acc[0][1] += av.x * bvv.y; acc[0][2] += av.x * bvv.z; acc[0][3] += av.x * bvv.w;
                acc[1][0] += av.y * bvv.x; acc[1][1] += av.y * bvv.y; acc[1][2] += av.y * bvv.z; acc[1][3] += av.y * bvv.w;
                acc[2][0] += av.z * bvv.x; acc[2][1] += av.z * bvv.y; acc[2][2] += av.z * bvv.z; acc[2][3] += av.z * bvv.w;
                acc[3][0] += av.w * bvv.x; acc[3][1] += av.w * bvv.y; acc[3][2] += av.w * bvv.z; acc[3][3] += av.w * bvv.w;
            }
            #pragma unroll
            for (int mm = 0; mm < 4; mm++) {
                int mglob = m0 + mg * 4 + mm;
                bool valid = (mglob < Mr);
                #pragma unroll
                for (int kk = 0; kk < 4; kk++) {
                    if (valid && acc[mm][kk] > bv[kk]) { bv[kk] = acc[mm][kk]; bm[kk] = mglob; }
                }
            }
        }
    }
    __syncthreads();
    #pragma unroll
    for (int kk = 0; kk < 4; kk++) { rv[mg][kg * 4 + kk] = bv[kk]; rm[mg][kg * 4 + kk] = bm[kk]; }
    __syncthreads();
    if (tx < 64) {
        float best = -FLT_MAX; int bi = 0x7fffffff;
        #pragma unroll
        for (int g = 0; g < 16; g++) {
            float v = rv[g][tx]; int m = rm[g][tx];
            if (v > best || (v == best && m < bi)) { best = v; bi = m; }
        }
        g_bestv[r][ch][k0 + tx] = best;
        g_bestm[r][ch][k0 + tx] = bi;
    }
}

// ---------------- Kernel M: merge chunk argmax, sigmoid, scatter-aggregate ----------------
__global__ __launch_bounds__(256) void kM(const float* __restrict__ sim_beta) {
    int r = blockIdx.y;
    int warp = threadIdx.x >> 5, lane = threadIdx.x & 31;
    int col = blockIdx.x * 8 + warp;
    int cnt = min(g_cnt[r], MCAP);
    float v = -FLT_MAX; int m = 0x7fffffff;
    if (lane < NCHUNK) { v = g_bestv[r][lane][col]; m = g_bestm[r][lane][col]; }
    #pragma unroll
    for (int off = 16; off > 0; off >>= 1) {
        float ov = __shfl_down_sync(0xffffffffu, v, off);
        int   om = __shfl_down_sync(0xffffffffu, m, off);
        if (ov > v || (ov == v && om < m)) { v = ov; m = om; }
    }
    v = __shfl_sync(0xffffffffu, v, 0);
    m = __shfl_sync(0xffffffffu, m, 0);
    if (m >= cnt) return;    // dead row won (or empty): column contributes nothing
    float s = sim_beta[0] + v * g_invx[r][col];
    float sim = 1.0f / (1.0f + expf(-s));
    atomicAdd(&g_agg[r][m][lane],      sim * g_valP[r][col][lane]);
    atomicAdd(&g_agg[r][m][lane + 32], sim * g_valP[r][col][lane + 32]);
    if (lane == 0) atomicAdd(&g_den[r][m], sim);
}

// ---------------- Kernel F: per-point output assembly + projection ----------------
__global__ __launch_bounds__(256) void kF(const float* __restrict__ Wp,
                                          const float* __restrict__ bp,
                                          float* __restrict__ out) {
    __shared__ float so[64][65];
    __shared__ float wp[64][65];
    __shared__ float bsh[64];
    __shared__ int   fl[64];
    int tx = threadIdx.x;
    int n0 = blockIdx.x * 64;
    #pragma unroll
    for (int j = 0; j < 16; j++) {
        int idx = tx + j * 256;
        int o = idx >> 6, c = idx & 63;
        wp[c][o] = Wp[idx];
    }
    if (tx < 64) { bsh[tx] = bp[tx]; fl[tx] = 0; }
    __syncthreads();
    {
        int pl = tx >> 2, cg = tx & 3;
        int n = n0 + pl;
        int r = g_pr[n];
        int lf = 0;
        if (r >= 0) {
            int pos = min(g_ppos[n], MCAP - 1);
            float den = g_den[r][pos] + 1.0f;
            #pragma unroll
            for (int j = 0; j < 16; j++) {
                int c = cg * 16 + j;
                float ov = (g_agg[r][pos][c] + g_vc[r][pos][c]) / den;
                so[pl][c] = ov;
                if (ov != 0.0f) lf = 1;
            }
        } else {
            #pragma unroll
            for (int j = 0; j < 16; j++) so[pl][cg * 16 + j] = 0.0f;
        }
        if (lf) atomicOr(&fl[pl], 1);
    }
    __syncthreads();
    int pl = tx & 63, og = tx >> 6;
    float mask = fl[pl] ? 1.0f : 0.0f;
    float acc[16];
    #pragma unroll
    for (int i = 0; i < 16; i++) acc[i] = 0.f;
    #pragma unroll
    for (int c = 0; c < 64; c++) {
        float xv = so[pl][c];
        #pragma unroll
        for (int i = 0; i < 16; i++) acc[i] += xv * wp[c][og * 16 + i];
    }
    #pragma unroll
    for (int i = 0; i < 16; i++) {
        int o = og * 16 + i;
        out[o * NP + n0 + pl] = (acc[i] + bsh[o]) * mask;
    }
}

// ---------------- launch ----------------
extern "C" void kernel_launch(void* const* d_in, const int* in_sizes, int n_in,
                              void* d_out, int out_size) {
    const float* points    = (const float*)d_in[0];
    const float* x         = (const float*)d_in[1];
    const float* W_f       = (const float*)d_in[2];
    const float* b_f       = (const float*)d_in[3];
    const float* W_v       = (const float*)d_in[4];
    const float* b_v       = (const float*)d_in[5];
    const float* W_proj    = (const float*)d_in[6];
    const float* b_proj    = (const float*)d_in[7];
    const float* sim_alpha = (const float*)d_in[8];
    const float* sim_beta  = (const float*)d_in[9];
    float* out = (float*)d_out;

    kA<<<HWP / 64, 256>>>(x, W_f, b_f, W_v, b_v);
    kB<<<(R4 * KP) / 8, 256>>>();
    kC<<<1, 1024>>>(points);
    kD<<<dim3(1025, R4), 128>>>(sim_alpha);
    kZ<<<(R4 * MCAP * C64 + 255) / 256, 256>>>();
    kE<<<dim3(KP / 64, NCHUNK, R4), 256>>>();
    kM<<<dim3(KP / 8, R4), 256>>>(sim_beta);
    kF<<<NP / 64, 256>>>(W_proj, b_proj, out);
}